// round 2
// baseline (speedup 1.0000x reference)
#include <cuda_runtime.h>
#include <cuda_bf16.h>

__device__ __forceinline__ void cov_elem(float sraw0, float sraw1, float sraw2,
                                         float4 q, float c[6])
{
    // s^2 = exp(2*raw): squaring folded into exponent
    float s0 = __expf(2.0f * sraw0);
    float s1 = __expf(2.0f * sraw1);
    float s2 = __expf(2.0f * sraw2);

    float inv = rsqrtf(q.x * q.x + q.y * q.y + q.z * q.z + q.w * q.w);
    float w = q.x * inv, x = q.y * inv, y = q.z * inv, z = q.w * inv;

    float r00 = 1.0f - 2.0f * (y * y + z * z);
    float r01 = 2.0f * (x * y - w * z);
    float r02 = 2.0f * (x * z + w * y);
    float r10 = 2.0f * (x * y + w * z);
    float r11 = 1.0f - 2.0f * (x * x + z * z);
    float r12 = 2.0f * (y * z - w * x);
    float r20 = 2.0f * (x * z - w * y);
    float r21 = 2.0f * (y * z + w * x);
    float r22 = 1.0f - 2.0f * (x * x + y * y);

    // cov[i][k] = sum_j R[i][j]*R[k][j]*s_j^2
    c[0] = r00 * r00 * s0 + r01 * r01 * s1 + r02 * r02 * s2;  // c00
    c[1] = r00 * r10 * s0 + r01 * r11 * s1 + r02 * r12 * s2;  // c01
    c[2] = r00 * r20 * s0 + r01 * r21 * s1 + r02 * r22 * s2;  // c02
    c[3] = r10 * r10 * s0 + r11 * r11 * s1 + r12 * r12 * s2;  // c11
    c[4] = r10 * r20 * s0 + r11 * r21 * s1 + r12 * r22 * s2;  // c12
    c[5] = r20 * r20 * s0 + r21 * r21 * s1 + r22 * r22 * s2;  // c22
}

// 4 elements per thread: all memory traffic is 128-bit, fully coalesced.
__global__ __launch_bounds__(256)
void gaussian_cov_vec4_kernel(const float4* __restrict__ sc4,   // scaling as float4 stream
                              const float4* __restrict__ rot,   // one float4 per element
                              float4* __restrict__ out4,        // output as float4 stream
                              int n)                            // element count
{
    int t = blockIdx.x * blockDim.x + threadIdx.x;
    int base = t * 4;
    if (base >= n) return;

    if (base + 4 <= n) {
        // Front-batched 128-bit loads (3 scaling + 4 rotation)
        float4 sa = sc4[3 * t + 0];  // elems: e0.{s0,s1,s2}, e1.s0
        float4 sb = sc4[3 * t + 1];  // e1.{s1,s2}, e2.{s0,s1}
        float4 sc = sc4[3 * t + 2];  // e2.s2, e3.{s0,s1,s2}
        float4 q0 = rot[base + 0];
        float4 q1 = rot[base + 1];
        float4 q2 = rot[base + 2];
        float4 q3 = rot[base + 3];

        float c0[6], c1[6], c2[6], c3[6];
        cov_elem(sa.x, sa.y, sa.z, q0, c0);
        cov_elem(sa.w, sb.x, sb.y, q1, c1);
        cov_elem(sb.z, sb.w, sc.x, q2, c2);
        cov_elem(sc.y, sc.z, sc.w, q3, c3);

        // 24 output floats = 6 float4 stores
        float4* o = out4 + 6 * t;
        o[0] = make_float4(c0[0], c0[1], c0[2], c0[3]);
        o[1] = make_float4(c0[4], c0[5], c1[0], c1[1]);
        o[2] = make_float4(c1[2], c1[3], c1[4], c1[5]);
        o[3] = make_float4(c2[0], c2[1], c2[2], c2[3]);
        o[4] = make_float4(c2[4], c2[5], c3[0], c3[1]);
        o[5] = make_float4(c3[2], c3[3], c3[4], c3[5]);
    } else {
        // Scalar tail (not hit for N=4M, kept for generality)
        const float* scal = (const float*)sc4;
        float* out = (float*)out4;
        for (int i = base; i < n; i++) {
            float c[6];
            cov_elem(scal[3 * i + 0], scal[3 * i + 1], scal[3 * i + 2], rot[i], c);
            for (int k = 0; k < 6; k++) out[6 * i + k] = c[k];
        }
    }
}

extern "C" void kernel_launch(void* const* d_in, const int* in_sizes, int n_in,
                              void* d_out, int out_size)
{
    const float4* sc4 = (const float4*)d_in[0];  // [N,3] float32
    const float4* rot = (const float4*)d_in[1];  // [N,4] float32
    float4*       out = (float4*)d_out;          // [N,6] float32

    int n = in_sizes[0] / 3;                 // N elements
    int nthreads_total = (n + 3) / 4;        // 4 elems per thread
    int threads = 256;
    int blocks = (nthreads_total + threads - 1) / threads;
    gaussian_cov_vec4_kernel<<<blocks, threads>>>(sc4, rot, out, n);
}

// round 3
// speedup vs baseline: 1.5039x; 1.5039x over previous
#include <cuda_runtime.h>
#include <cuda_bf16.h>

struct Cov6 { float c00, c01, c02, c11, c12, c22; };

__device__ __forceinline__ Cov6 cov_elem(float sraw0, float sraw1, float sraw2, float4 q)
{
    // s^2 = exp(2*raw): squaring folded into exponent
    float s0 = __expf(2.0f * sraw0);
    float s1 = __expf(2.0f * sraw1);
    float s2 = __expf(2.0f * sraw2);

    float inv = rsqrtf(q.x * q.x + q.y * q.y + q.z * q.z + q.w * q.w);
    float w = q.x * inv, x = q.y * inv, y = q.z * inv, z = q.w * inv;

    float r00 = 1.0f - 2.0f * (y * y + z * z);
    float r01 = 2.0f * (x * y - w * z);
    float r02 = 2.0f * (x * z + w * y);
    float r10 = 2.0f * (x * y + w * z);
    float r11 = 1.0f - 2.0f * (x * x + z * z);
    float r12 = 2.0f * (y * z - w * x);
    float r20 = 2.0f * (x * z - w * y);
    float r21 = 2.0f * (y * z + w * x);
    float r22 = 1.0f - 2.0f * (x * x + y * y);

    Cov6 c;
    c.c00 = r00 * r00 * s0 + r01 * r01 * s1 + r02 * r02 * s2;
    c.c01 = r00 * r10 * s0 + r01 * r11 * s1 + r02 * r12 * s2;
    c.c02 = r00 * r20 * s0 + r01 * r21 * s1 + r02 * r22 * s2;
    c.c11 = r10 * r10 * s0 + r11 * r11 * s1 + r12 * r12 * s2;
    c.c12 = r10 * r20 * s0 + r11 * r21 * s1 + r12 * r22 * s2;
    c.c22 = r20 * r20 * s0 + r21 * r21 * s1 + r22 * r22 * s2;
    return c;
}

// 2 elements per thread: scaling via 3x LDG.64, rot via 2x LDG.128,
// output via exactly 3x STG.128 (12 floats / thread, 16B aligned).
__global__ __launch_bounds__(256)
void gaussian_cov_vec2_kernel(const float2* __restrict__ sc2,
                              const float4* __restrict__ rot,
                              float4* __restrict__ out4,
                              int n)
{
    int t = blockIdx.x * blockDim.x + threadIdx.x;
    int base = t * 2;
    if (base >= n) return;

    if (base + 2 <= n) {
        // Front-batched loads
        float2 sa = sc2[3 * t + 0];   // e0.s0, e0.s1
        float2 sb = sc2[3 * t + 1];   // e0.s2, e1.s0
        float2 sc = sc2[3 * t + 2];   // e1.s1, e1.s2
        float4 q0 = rot[base + 0];
        float4 q1 = rot[base + 1];

        Cov6 a = cov_elem(sa.x, sa.y, sb.x, q0);
        Cov6 b = cov_elem(sb.y, sc.x, sc.y, q1);

        float4* o = out4 + 3 * t;
        o[0] = make_float4(a.c00, a.c01, a.c02, a.c11);
        o[1] = make_float4(a.c12, a.c22, b.c00, b.c01);
        o[2] = make_float4(b.c02, b.c11, b.c12, b.c22);
    } else {
        // Scalar tail (n odd; not hit for N=4M)
        const float* scal = (const float*)sc2;
        float* out = (float*)out4;
        int i = base;
        Cov6 c = cov_elem(scal[3 * i + 0], scal[3 * i + 1], scal[3 * i + 2], rot[i]);
        out[6 * i + 0] = c.c00; out[6 * i + 1] = c.c01; out[6 * i + 2] = c.c02;
        out[6 * i + 3] = c.c11; out[6 * i + 4] = c.c12; out[6 * i + 5] = c.c22;
    }
}

extern "C" void kernel_launch(void* const* d_in, const int* in_sizes, int n_in,
                              void* d_out, int out_size)
{
    const float2* sc2 = (const float2*)d_in[0];  // [N,3] float32
    const float4* rot = (const float4*)d_in[1];  // [N,4] float32
    float4*       out = (float4*)d_out;          // [N,6] float32

    int n = in_sizes[0] / 3;                // N elements
    int nthreads_total = (n + 1) / 2;       // 2 elems per thread
    int threads = 256;
    int blocks = (nthreads_total + threads - 1) / threads;
    gaussian_cov_vec2_kernel<<<blocks, threads>>>(sc2, rot, out, n);
}

// round 4
// speedup vs baseline: 1.5132x; 1.0061x over previous
#include <cuda_runtime.h>
#include <cuda_bf16.h>

struct Cov6 { float c00, c01, c02, c11, c12, c22; };

__device__ __forceinline__ Cov6 cov_elem(float sraw0, float sraw1, float sraw2, float4 q)
{
    // s^2 = exp(2*raw): squaring folded into exponent
    float s0 = __expf(2.0f * sraw0);
    float s1 = __expf(2.0f * sraw1);
    float s2 = __expf(2.0f * sraw2);

    float inv = rsqrtf(q.x * q.x + q.y * q.y + q.z * q.z + q.w * q.w);
    float w = q.x * inv, x = q.y * inv, y = q.z * inv, z = q.w * inv;

    float r00 = 1.0f - 2.0f * (y * y + z * z);
    float r01 = 2.0f * (x * y - w * z);
    float r02 = 2.0f * (x * z + w * y);
    float r10 = 2.0f * (x * y + w * z);
    float r11 = 1.0f - 2.0f * (x * x + z * z);
    float r12 = 2.0f * (y * z - w * x);
    float r20 = 2.0f * (x * z - w * y);
    float r21 = 2.0f * (y * z + w * x);
    float r22 = 1.0f - 2.0f * (x * x + y * y);

    Cov6 c;
    c.c00 = r00 * r00 * s0 + r01 * r01 * s1 + r02 * r02 * s2;
    c.c01 = r00 * r10 * s0 + r01 * r11 * s1 + r02 * r12 * s2;
    c.c02 = r00 * r20 * s0 + r01 * r21 * s1 + r02 * r22 * s2;
    c.c11 = r10 * r10 * s0 + r11 * r11 * s1 + r12 * r12 * s2;
    c.c12 = r10 * r20 * s0 + r11 * r21 * s1 + r12 * r22 * s2;
    c.c22 = r20 * r20 * s0 + r21 * r21 * s1 + r22 * r22 * s2;
    return c;
}

// 2 elements per thread. __launch_bounds__(256, 4) raises the ptxas register
// budget to 64 so the 5 front-batched loads actually materialize as MLP
// (rounds 2-3 showed the default budget of 32 regs serializes them).
__global__ __launch_bounds__(256, 4)
void gaussian_cov_vec2_kernel(const float2* __restrict__ sc2,
                              const float4* __restrict__ rot,
                              float4* __restrict__ out4,
                              int n)
{
    int t = blockIdx.x * blockDim.x + threadIdx.x;
    int base = t * 2;
    if (base >= n) return;

    if (base + 2 <= n) {
        // Front-batched loads: 3x LDG.64 + 2x LDG.128, all independent
        float2 sa = sc2[3 * t + 0];   // e0.s0, e0.s1
        float2 sb = sc2[3 * t + 1];   // e0.s2, e1.s0
        float2 sc = sc2[3 * t + 2];   // e1.s1, e1.s2
        float4 q0 = rot[base + 0];
        float4 q1 = rot[base + 1];

        Cov6 a = cov_elem(sa.x, sa.y, sb.x, q0);
        Cov6 b = cov_elem(sb.y, sc.x, sc.y, q1);

        float4* o = out4 + 3 * t;
        o[0] = make_float4(a.c00, a.c01, a.c02, a.c11);
        o[1] = make_float4(a.c12, a.c22, b.c00, b.c01);
        o[2] = make_float4(b.c02, b.c11, b.c12, b.c22);
    } else {
        // Scalar tail (n odd; not hit for N=4M)
        const float* scal = (const float*)sc2;
        float* out = (float*)out4;
        int i = base;
        Cov6 c = cov_elem(scal[3 * i + 0], scal[3 * i + 1], scal[3 * i + 2], rot[i]);
        out[6 * i + 0] = c.c00; out[6 * i + 1] = c.c01; out[6 * i + 2] = c.c02;
        out[6 * i + 3] = c.c11; out[6 * i + 4] = c.c12; out[6 * i + 5] = c.c22;
    }
}

extern "C" void kernel_launch(void* const* d_in, const int* in_sizes, int n_in,
                              void* d_out, int out_size)
{
    const float2* sc2 = (const float2*)d_in[0];  // [N,3] float32
    const float4* rot = (const float4*)d_in[1];  // [N,4] float32
    float4*       out = (float4*)d_out;          // [N,6] float32

    int n = in_sizes[0] / 3;                // N elements
    int nthreads_total = (n + 1) / 2;       // 2 elems per thread
    int threads = 256;
    int blocks = (nthreads_total + threads - 1) / threads;
    gaussian_cov_vec2_kernel<<<blocks, threads>>>(sc2, rot, out, n);
}